// round 1
// baseline (speedup 1.0000x reference)
#include <cuda_runtime.h>
#include <cuda_bf16.h>

#define N_SPK 1024
#define M_UTT 32
#define M_ENR 16
#define M_TST 16
#define D     512
#define NT    (N_SPK * M_TST)   /* 16384 test rows */
#define EPSV  1e-8f

// ---------------- scratch (static __device__ globals: allowed) ----------------
__device__ float g_cent[N_SPK * D];     // normalized centroids   (2 MB)
__device__ float g_test[NT * D];        // normalized test rows   (32 MB)
__device__ float g_part[N_SPK * 128];   // per-(row, colblock) exp-sum partials (512 KB)
__device__ float g_pos[N_SPK];          // positive sums

__device__ __forceinline__ float warp_sum(float v) {
#pragma unroll
    for (int o = 16; o > 0; o >>= 1) v += __shfl_xor_sync(0xffffffffu, v, o);
    return v;
}

// ---------------- kernel 1: centroid mean + L2 normalize ----------------
// one block (512 threads) per speaker; thread d handles dimension d
__global__ void prep_cent_kernel(const float* __restrict__ emb) {
    int spk = blockIdx.x;
    int d   = threadIdx.x;
    const float* base = emb + (size_t)spk * M_UTT * D + d;
    float s = 0.f;
#pragma unroll
    for (int u = 0; u < M_ENR; u++) s += base[u * D];
    float c = s * (1.0f / (float)M_ENR);

    // block-reduce sum of squares (512 threads = 16 warps)
    __shared__ float red[16];
    __shared__ float s_inv;
    float ss = warp_sum(c * c);
    int w = threadIdx.x >> 5, l = threadIdx.x & 31;
    if (l == 0) red[w] = ss;
    __syncthreads();
    if (w == 0) {
        float v = (l < 16) ? red[l] : 0.f;
        v = warp_sum(v);
        if (l == 0) s_inv = 1.0f / fmaxf(sqrtf(v), EPSV);
    }
    __syncthreads();
    g_cent[spk * D + d] = c * s_inv;
}

// ---------------- kernel 2: normalize test rows ----------------
// one block (512 threads) per test row r = spk*16 + t  -> emb row spk*32 + 16 + t
__global__ void prep_test_kernel(const float* __restrict__ emb) {
    int r   = blockIdx.x;
    int spk = r >> 4;
    int t   = r & 15;
    int d   = threadIdx.x;
    float v = emb[((size_t)spk * M_UTT + M_ENR + t) * D + d];

    __shared__ float red[16];
    __shared__ float s_inv;
    float ss = warp_sum(v * v);
    int w = threadIdx.x >> 5, l = threadIdx.x & 31;
    if (l == 0) red[w] = ss;
    __syncthreads();
    if (w == 0) {
        float x = (l < 16) ? red[l] : 0.f;
        x = warp_sum(x);
        if (l == 0) s_inv = 1.0f / fmaxf(sqrtf(x), EPSV);
    }
    __syncthreads();
    g_test[(size_t)r * D + d] = v * s_inv;
}

// ---------------- kernel 3: positive sums ----------------
// one block (512 threads = 16 warps) per speaker; warp w computes dot for test t=w
__global__ void pos_kernel(const float* __restrict__ alpha_p,
                           const float* __restrict__ beta_p) {
    int spk = blockIdx.x;
    int w = threadIdx.x >> 5, l = threadIdx.x & 31;
    const float* c = g_cent + spk * D;
    const float* t = g_test + (size_t)(spk * M_TST + w) * D;
    float s = 0.f;
#pragma unroll
    for (int q = 0; q < 16; q++) s += c[l + q * 32] * t[l + q * 32];
    s = warp_sum(s);
    __shared__ float sm[16];
    if (l == 0) sm[w] = __expf((*alpha_p) * s + (*beta_p));
    __syncthreads();
    if (threadIdx.x == 0) {
        float p = 0.f;
#pragma unroll
        for (int i = 0; i < 16; i++) p += sm[i];
        g_pos[spk] = p;
    }
}

// ---------------- kernel 4: fused GEMM + exp + row reduce ----------------
// S[i, jt] = dot(cent_n[i], test_n[jt]);  accumulate sum_jt exp(alpha*S + beta)
// tile 128x128, BK=16, 256 threads, 8x8 per thread. Deterministic: each block
// writes its own column-block partial; no atomics.
#define BM 128
#define BN 128
#define BK 16
#define TM 8
#define TN 8

__global__ __launch_bounds__(256, 2)
void gemm_kernel(const float* __restrict__ alpha_p,
                 const float* __restrict__ beta_p) {
    const int bi  = blockIdx.y;   // 0..7   (row block over 1024 centroids)
    const int bj  = blockIdx.x;   // 0..127 (col block over 16384 tests)
    const int tid = threadIdx.x;  // 256

    __shared__ float As[BK][BM + 1];
    __shared__ float Bs[BK][BN + 1];

    const int ty = tid >> 4;      // 0..15
    const int tx = tid & 15;      // 0..15

    const float alpha = *alpha_p;
    const float beta  = *beta_p;

    const int arow0 = bi * BM;
    const int brow0 = bj * BN;

    float acc[TM][TN];
#pragma unroll
    for (int m = 0; m < TM; m++)
#pragma unroll
        for (int n = 0; n < TN; n++) acc[m][n] = 0.f;

    for (int k0 = 0; k0 < D; k0 += BK) {
        // cooperative loads: 128 rows x 16 k = 512 float4, 2 per thread
#pragma unroll
        for (int i = 0; i < 2; i++) {
            int f4  = tid + i * 256;
            int row = f4 >> 2;     // 0..127
            int kq  = f4 & 3;      // 0..3  (4 floats each)
            float4 va = *(const float4*)&g_cent[(size_t)(arow0 + row) * D + k0 + kq * 4];
            As[kq * 4 + 0][row] = va.x;
            As[kq * 4 + 1][row] = va.y;
            As[kq * 4 + 2][row] = va.z;
            As[kq * 4 + 3][row] = va.w;
            float4 vb = *(const float4*)&g_test[(size_t)(brow0 + row) * D + k0 + kq * 4];
            Bs[kq * 4 + 0][row] = vb.x;
            Bs[kq * 4 + 1][row] = vb.y;
            Bs[kq * 4 + 2][row] = vb.z;
            Bs[kq * 4 + 3][row] = vb.w;
        }
        __syncthreads();

#pragma unroll
        for (int k = 0; k < BK; k++) {
            float a[TM], b[TN];
#pragma unroll
            for (int m = 0; m < TM; m++) a[m] = As[k][ty * TM + m];
#pragma unroll
            for (int n = 0; n < TN; n++) b[n] = Bs[k][tx * TN + n];
#pragma unroll
            for (int m = 0; m < TM; m++)
#pragma unroll
                for (int n = 0; n < TN; n++) acc[m][n] = fmaf(a[m], b[n], acc[m][n]);
        }
        __syncthreads();
    }

    // epilogue: exp + reduce over this block's 128 columns
    float rowsum[TM];
#pragma unroll
    for (int m = 0; m < TM; m++) {
        float s = 0.f;
#pragma unroll
        for (int n = 0; n < TN; n++) s += __expf(fmaf(alpha, acc[m][n], beta));
        rowsum[m] = s;
    }
    // reduce across tx (lanes sharing the same ty; tx = low 4 bits of lane id)
#pragma unroll
    for (int o = 1; o < 16; o <<= 1)
#pragma unroll
        for (int m = 0; m < TM; m++)
            rowsum[m] += __shfl_xor_sync(0xffffffffu, rowsum[m], o);

    if (tx == 0) {
#pragma unroll
        for (int m = 0; m < TM; m++)
            g_part[(arow0 + ty * TM + m) * 128 + bj] = rowsum[m];
    }
}

// ---------------- kernel 5: finalize (per-row totals, log terms, mean) --------
__global__ void finalize_kernel(float* __restrict__ out) {
    int i = threadIdx.x;   // 1024 threads, one per speaker
    float tot = 0.f;
    const float* p = g_part + i * 128;
#pragma unroll 8
    for (int b = 0; b < 128; b++) tot += p[b];
    float pos  = g_pos[i];
    float term = logf(tot - pos) - logf(pos);

    __shared__ float red[32];
    term = warp_sum(term);
    int w = threadIdx.x >> 5, l = threadIdx.x & 31;
    if (l == 0) red[w] = term;
    __syncthreads();
    if (w == 0) {
        float v = red[l];
        v = warp_sum(v);
        if (l == 0) out[0] = v * (1.0f / (float)N_SPK);
    }
}

// ---------------- launch ----------------
extern "C" void kernel_launch(void* const* d_in, const int* in_sizes, int n_in,
                              void* d_out, int out_size) {
    const float* emb     = (const float*)d_in[0];
    // d_in[1] = labels (int64) — ordering is implied by layout; unused.
    const float* alpha_p = (const float*)d_in[2];
    const float* beta_p  = (const float*)d_in[3];
    float* out = (float*)d_out;

    prep_cent_kernel<<<N_SPK, 512>>>(emb);
    prep_test_kernel<<<NT, 512>>>(emb);
    pos_kernel<<<N_SPK, 512>>>(alpha_p, beta_p);
    gemm_kernel<<<dim3(128, 8), 256>>>(alpha_p, beta_p);
    finalize_kernel<<<1, 1024>>>(out);
}

// round 3
// speedup vs baseline: 3.5665x; 3.5665x over previous
#include <cuda_runtime.h>
#include <cuda_bf16.h>
#include <cstdint>

#define N_SPK 1024
#define M_UTT 32
#define M_ENR 16
#define M_TST 16
#define D     512
#define NT    (N_SPK * M_TST)   /* 16384 test rows */
#define EPSV  1e-8f

// ---------------- scratch ----------------
__device__ __nv_bfloat16  g_centb[N_SPK * D];     // bf16 normalized centroids (1 MB)
__device__ __nv_bfloat16  g_testb[NT * D];        // bf16 normalized test rows (16 MB)
__device__ float          g_part[N_SPK * 128];    // per-(row, colblock) exp-sums (512 KB)
__device__ float          g_pos[N_SPK];

__device__ __forceinline__ float warp_sum(float v) {
#pragma unroll
    for (int o = 16; o > 0; o >>= 1) v += __shfl_xor_sync(0xffffffffu, v, o);
    return v;
}
__device__ __forceinline__ uint32_t smem_u32(const void* p) {
    uint32_t a;
    asm("{ .reg .u64 t; cvta.to.shared.u64 t, %1; cvt.u32.u64 %0, t; }" : "=r"(a) : "l"(p));
    return a;
}

// ---------------- kernel 1: centroid mean + L2 normalize -> bf16 ----------------
// block 128 threads per speaker; thread handles 4 dims (float4)
__global__ __launch_bounds__(128)
void prep_cent_kernel(const float* __restrict__ emb) {
    const int spk = blockIdx.x;
    const int d4  = threadIdx.x * 4;
    const float* base = emb + (size_t)spk * M_UTT * D + d4;
    float4 a = make_float4(0.f, 0.f, 0.f, 0.f);
#pragma unroll
    for (int u = 0; u < M_ENR; u++) {
        float4 v = *(const float4*)(base + (size_t)u * D);
        a.x += v.x; a.y += v.y; a.z += v.z; a.w += v.w;
    }
    const float inv = 1.0f / (float)M_ENR;
    a.x *= inv; a.y *= inv; a.z *= inv; a.w *= inv;

    __shared__ float red[4];
    __shared__ float s_inv;
    float ss = warp_sum(a.x * a.x + a.y * a.y + a.z * a.z + a.w * a.w);
    int w = threadIdx.x >> 5, l = threadIdx.x & 31;
    if (l == 0) red[w] = ss;
    __syncthreads();
    if (threadIdx.x == 0) {
        float v = red[0] + red[1] + red[2] + red[3];
        s_inv = 1.0f / fmaxf(sqrtf(v), EPSV);
    }
    __syncthreads();
    const float s = s_inv;
    __nv_bfloat162 p0 = __float22bfloat162_rn(make_float2(a.x * s, a.y * s));
    __nv_bfloat162 p1 = __float22bfloat162_rn(make_float2(a.z * s, a.w * s));
    *(__nv_bfloat162*)&g_centb[spk * D + d4]     = p0;
    *(__nv_bfloat162*)&g_centb[spk * D + d4 + 2] = p1;
}

// ---------------- kernel 2: normalize test rows -> bf16 (warp per row) --------
__global__ __launch_bounds__(256)
void prep_test_kernel(const float* __restrict__ emb) {
    const int wid  = threadIdx.x >> 5;
    const int lane = threadIdx.x & 31;
    const int r    = blockIdx.x * 8 + wid;          // 0..16383
    const int spk  = r >> 4;
    const int t    = r & 15;
    const float* src = emb + ((size_t)spk * M_UTT + M_ENR + t) * D;

    float4 v[4];
    float ss = 0.f;
#pragma unroll
    for (int q = 0; q < 4; q++) {
        v[q] = *(const float4*)(src + 4 * (lane + q * 32));
        ss += v[q].x * v[q].x + v[q].y * v[q].y + v[q].z * v[q].z + v[q].w * v[q].w;
    }
    ss = warp_sum(ss);
    const float s = 1.0f / fmaxf(sqrtf(ss), EPSV);
    __nv_bfloat16* dst = g_testb + (size_t)r * D;
#pragma unroll
    for (int q = 0; q < 4; q++) {
        __nv_bfloat162 p0 = __float22bfloat162_rn(make_float2(v[q].x * s, v[q].y * s));
        __nv_bfloat162 p1 = __float22bfloat162_rn(make_float2(v[q].z * s, v[q].w * s));
        *(__nv_bfloat162*)&dst[4 * (lane + q * 32)]     = p0;
        *(__nv_bfloat162*)&dst[4 * (lane + q * 32) + 2] = p1;
    }
}

// ---------------- kernel 3: positive sums (bf16 inputs, fp32 accumulate) -------
__global__ __launch_bounds__(512)
void pos_kernel(const float* __restrict__ alpha_p,
                const float* __restrict__ beta_p) {
    const int spk = blockIdx.x;
    const int w = threadIdx.x >> 5, l = threadIdx.x & 31;
    const __nv_bfloat16* c = g_centb + spk * D;
    const __nv_bfloat16* t = g_testb + (size_t)(spk * M_TST + w) * D;
    float s = 0.f;
#pragma unroll
    for (int q = 0; q < 8; q++) {
        __nv_bfloat162 cv = *(const __nv_bfloat162*)&c[2 * (l + q * 32)];
        __nv_bfloat162 tv = *(const __nv_bfloat162*)&t[2 * (l + q * 32)];
        s += __bfloat162float(cv.x) * __bfloat162float(tv.x)
           + __bfloat162float(cv.y) * __bfloat162float(tv.y);
    }
    s = warp_sum(s);
    __shared__ float sm[16];
    if (l == 0) sm[w] = __expf((*alpha_p) * s + (*beta_p));
    __syncthreads();
    if (threadIdx.x == 0) {
        float p = 0.f;
#pragma unroll
        for (int i = 0; i < 16; i++) p += sm[i];
        g_pos[spk] = p;
    }
}

// ---------------- kernel 4: HMMA bf16 GEMM + exp + row reduce ----------------
// mma.sync.m16n8k16 row.col (A: [M,K] K-major, B: [N,K] K-major -> A @ B^T)
// Tile 128x128, BK=32, 256 threads (2x4 warps, 64x32 per warp), cp.async 2-stage.
#define BM 128
#define BN 128
#define BK 32
#define RS 40                     /* smem row stride in bf16 (80 B): conflict-free */
#define NITER (D / BK)            /* 16 */

__device__ __forceinline__ void mma_bf16(float* c, const uint32_t* a, const uint32_t* b) {
    asm volatile(
        "mma.sync.aligned.m16n8k16.row.col.f32.bf16.bf16.f32 "
        "{%0,%1,%2,%3}, {%4,%5,%6,%7}, {%8,%9}, {%0,%1,%2,%3};"
        : "+f"(c[0]), "+f"(c[1]), "+f"(c[2]), "+f"(c[3])
        : "r"(a[0]), "r"(a[1]), "r"(a[2]), "r"(a[3]), "r"(b[0]), "r"(b[1]));
}
#define CP_ASYNC16(dst, src) \
    asm volatile("cp.async.ca.shared.global [%0], [%1], 16;" :: "r"(dst), "l"(src))
#define CP_COMMIT() asm volatile("cp.async.commit_group;" ::: "memory")
#define CP_WAIT(n)  asm volatile("cp.async.wait_group %0;" :: "n"(n) : "memory")

__global__ __launch_bounds__(256, 1)
void gemm_mma_kernel(const float* __restrict__ alpha_p,
                     const float* __restrict__ beta_p) {
    __shared__ __align__(16) __nv_bfloat16 As[2][BM * RS];
    __shared__ __align__(16) __nv_bfloat16 Bs[2][BN * RS];
    __shared__ float red[BM * 4];

    const int tid  = threadIdx.x;
    const int wid  = tid >> 5;
    const int lane = tid & 31;
    const int bj   = blockIdx.x;     // 0..127 (column block, 128 test rows)
    const int bi   = blockIdx.y;     // 0..7   (row block, 128 centroids)

    const int warp_m = wid >> 2;     // 0..1  -> 64-row slab
    const int warp_n = wid & 3;      // 0..3  -> 32-col slab

    const float alpha = *alpha_p;
    const float beta  = *beta_p;

    const __nv_bfloat16* Ag = g_centb + (size_t)bi * BM * D;
    const __nv_bfloat16* Bg = g_testb + (size_t)bj * BN * D;

    const uint32_t sA[2] = { smem_u32(&As[0][0]), smem_u32(&As[1][0]) };
    const uint32_t sB[2] = { smem_u32(&Bs[0][0]), smem_u32(&Bs[1][0]) };

    // cooperative cp.async mapping: idx -> (row, 16B chunk of 4)
    const int ldrow = tid >> 2;       // 0..63  base row (2 iters: +64)
    const int ldchk = tid & 3;        // 0..3

    float c[4][4][4];
#pragma unroll
    for (int mi = 0; mi < 4; mi++)
#pragma unroll
        for (int nf = 0; nf < 4; nf++)
#pragma unroll
            for (int q = 0; q < 4; q++) c[mi][nf][q] = 0.f;

    // ldmatrix per-lane address components (bytes)
    const uint32_t a_row = (uint32_t)(warp_m * 64 + (lane & 15)) * (RS * 2);
    const uint32_t a_col = (uint32_t)((lane >> 4) * 8) * 2;
    const uint32_t b_row = (uint32_t)(warp_n * 32 + (lane & 7)) * (RS * 2);
    const uint32_t b_col = (uint32_t)(((lane >> 3) & 1) * 8) * 2;

    // prologue: stage 0
    {
        const int k0 = 0;
#pragma unroll
        for (int h = 0; h < 2; h++) {
            int row = ldrow + h * 64;
            CP_ASYNC16(sA[0] + row * (RS * 2) + ldchk * 16,
                       Ag + (size_t)row * D + k0 + ldchk * 8);
            CP_ASYNC16(sB[0] + row * (RS * 2) + ldchk * 16,
                       Bg + (size_t)row * D + k0 + ldchk * 8);
        }
        CP_COMMIT();
    }

    for (int it = 0; it < NITER; it++) {
        const int cur = it & 1;
        if (it + 1 < NITER) {
            const int nxt = (it + 1) & 1;
            const int k0  = (it + 1) * BK;
#pragma unroll
            for (int h = 0; h < 2; h++) {
                int row = ldrow + h * 64;
                CP_ASYNC16(sA[nxt] + row * (RS * 2) + ldchk * 16,
                           Ag + (size_t)row * D + k0 + ldchk * 8);
                CP_ASYNC16(sB[nxt] + row * (RS * 2) + ldchk * 16,
                           Bg + (size_t)row * D + k0 + ldchk * 8);
            }
            CP_COMMIT();
            CP_WAIT(1);
        } else {
            CP_WAIT(0);
        }
        __syncthreads();

#pragma unroll
        for (int ks = 0; ks < 2; ks++) {
            uint32_t a[4][4], b[4][2];
#pragma unroll
            for (int mi = 0; mi < 4; mi++) {
                uint32_t addr = sA[cur] + a_row + (uint32_t)mi * 16 * (RS * 2)
                              + a_col + (uint32_t)ks * 32;
                asm volatile("ldmatrix.sync.aligned.m8n8.x4.shared.b16 "
                             "{%0,%1,%2,%3}, [%4];"
                             : "=r"(a[mi][0]), "=r"(a[mi][1]),
                               "=r"(a[mi][2]), "=r"(a[mi][3]) : "r"(addr));
            }
#pragma unroll
            for (int nf = 0; nf < 4; nf++) {
                uint32_t addr = sB[cur] + b_row + (uint32_t)nf * 8 * (RS * 2)
                              + b_col + (uint32_t)ks * 32;
                asm volatile("ldmatrix.sync.aligned.m8n8.x2.shared.b16 "
                             "{%0,%1}, [%2];"
                             : "=r"(b[nf][0]), "=r"(b[nf][1]) : "r"(addr));
            }
#pragma unroll
            for (int mi = 0; mi < 4; mi++)
#pragma unroll
                for (int nf = 0; nf < 4; nf++)
                    mma_bf16(c[mi][nf], a[mi], b[nf]);
        }
        __syncthreads();
    }

    // epilogue: exp + row sums.
    // thread owns rows r0 = warp_m*64 + mi*16 + lane/4 and r0+8 (cols: 2 per nf)
#pragma unroll
    for (int mi = 0; mi < 4; mi++) {
        float s0 = 0.f, s1 = 0.f;
#pragma unroll
        for (int nf = 0; nf < 4; nf++) {
            s0 += __expf(fmaf(alpha, c[mi][nf][0], beta))
                + __expf(fmaf(alpha, c[mi][nf][1], beta));
            s1 += __expf(fmaf(alpha, c[mi][nf][2], beta))
                + __expf(fmaf(alpha, c[mi][nf][3], beta));
        }
        s0 += __shfl_xor_sync(0xffffffffu, s0, 1);
        s0 += __shfl_xor_sync(0xffffffffu, s0, 2);
        s1 += __shfl_xor_sync(0xffffffffu, s1, 1);
        s1 += __shfl_xor_sync(0xffffffffu, s1, 2);
        if ((lane & 3) == 0) {
            int r0 = warp_m * 64 + mi * 16 + (lane >> 2);
            red[r0 * 4 + warp_n]       = s0;
            red[(r0 + 8) * 4 + warp_n] = s1;
        }
    }
    __syncthreads();
    if (tid < BM) {
        float tot = red[tid * 4] + red[tid * 4 + 1] + red[tid * 4 + 2] + red[tid * 4 + 3];
        g_part[(bi * BM + tid) * 128 + bj] = tot;
    }
}

// ---------------- kernel 5: finalize ----------------
__global__ void finalize_kernel(float* __restrict__ out) {
    int i = threadIdx.x;   // 1024 threads, one per speaker
    float tot = 0.f;
    const float* p = g_part + i * 128;
#pragma unroll 8
    for (int b = 0; b < 128; b++) tot += p[b];
    float pos  = g_pos[i];
    float term = logf(tot - pos) - logf(pos);

    __shared__ float red[32];
    term = warp_sum(term);
    int w = threadIdx.x >> 5, l = threadIdx.x & 31;
    if (l == 0) red[w] = term;
    __syncthreads();
    if (w == 0) {
        float v = red[l];
        v = warp_sum(v);
        if (l == 0) out[0] = v * (1.0f / (float)N_SPK);
    }
}

// ---------------- launch ----------------
extern "C" void kernel_launch(void* const* d_in, const int* in_sizes, int n_in,
                              void* d_out, int out_size) {
    const float* emb     = (const float*)d_in[0];
    const float* alpha_p = (const float*)d_in[2];
    const float* beta_p  = (const float*)d_in[3];
    float* out = (float*)d_out;

    prep_cent_kernel<<<N_SPK, 128>>>(emb);
    prep_test_kernel<<<NT / 8, 256>>>(emb);
    pos_kernel<<<N_SPK, 512>>>(alpha_p, beta_p);
    gemm_mma_kernel<<<dim3(128, 8), 256>>>(alpha_p, beta_p);
    finalize_kernel<<<1, 1024>>>(out);
}